// round 15
// baseline (speedup 1.0000x reference)
#include <cuda_runtime.h>
#include <cuda_bf16.h>
#include <math.h>
#include <stdint.h>

// Problem constants
#define B_      64
#define S_      256
#define INDIM_  512
#define MEM_    256
#define HEADS_  8
#define TOPK_   200
#define XLD     1024
#define QKLD    2304        // row stride of merged [Q|K|xw] output (covers 2*1024+256)
#define BS_     (B_ * S_)

typedef __nv_bfloat16 bf16;

// ---------------- static device scratch (no allocations allowed) ----------------
__device__ bf16  g_xh[BS_ * XLD];
__device__ bf16  g_xl[BS_ * XLD];
__device__ bf16  g_qkh[BS_ * QKLD];     // merged Q|K|xw hi (75 MB)
__device__ bf16  g_qkl[BS_ * QKLD];     // merged Q|K|xw lo
__device__ bf16  g_a2h[B_ * S_ * S_];
__device__ bf16  g_a2l[B_ * S_ * S_];
__device__ bf16  g_adjh[B_ * S_ * S_];
__device__ bf16  g_adjl[B_ * S_ * S_];
__device__ bf16  g_xwh[BS_ * MEM_];     // layer-0 xw only
__device__ bf16  g_xwl[BS_ * MEM_];
__device__ bf16  g_xwth[BS_ * MEM_];
__device__ bf16  g_xwtl[BS_ * MEM_];
__device__ bf16  g_wth[4 * 1024 * 1024];
__device__ bf16  g_wtl[4 * 1024 * 1024];
__device__ float g_biasqk[2560];
__device__ float g_scores[B_ * HEADS_ * S_ * S_];
__device__ float g_a[B_ * S_ * S_];
__device__ float g_t2[BS_ * MEM_];
__device__ float g_denom[BS_];
__device__ float g_thr[B_];
__device__ float g_pad[BS_];
__device__ int   g_maskkind;

// ---------------- small helpers ----------------
__device__ __forceinline__ uint32_t smem_u32(const void* p) {
    uint32_t a;
    asm("{ .reg .u64 t; cvta.to.shared.u64 t, %1; cvt.u32.u64 %0, t; }" : "=r"(a) : "l"(p));
    return a;
}
__device__ __forceinline__ void ldsm4(uint32_t* r, uint32_t addr) {
    asm volatile("ldmatrix.sync.aligned.m8n8.x4.shared.b16 {%0,%1,%2,%3}, [%4];"
                 : "=r"(r[0]), "=r"(r[1]), "=r"(r[2]), "=r"(r[3]) : "r"(addr));
}
__device__ __forceinline__ void sts128(uint32_t addr, uint4 v) {
    asm volatile("st.shared.v4.b32 [%0], {%1,%2,%3,%4};"
                 :: "r"(addr), "r"(v.x), "r"(v.y), "r"(v.z), "r"(v.w) : "memory");
}
__device__ __forceinline__ void mma16816(float* d, const uint32_t* a, uint32_t b0, uint32_t b1) {
    asm volatile("mma.sync.aligned.m16n8k16.row.col.f32.bf16.bf16.f32 "
                 "{%0,%1,%2,%3}, {%4,%5,%6,%7}, {%8,%9}, {%0,%1,%2,%3};"
                 : "+f"(d[0]), "+f"(d[1]), "+f"(d[2]), "+f"(d[3])
                 : "r"(a[0]), "r"(a[1]), "r"(a[2]), "r"(a[3]), "r"(b0), "r"(b1));
}
__device__ __forceinline__ void splitf(float v, bf16& h, bf16& l) {
    h = __float2bfloat16(v);
    l = __float2bfloat16(v - __bfloat162float(h));
}

// ---------------- bf16-split tensor-core GEMM (R8 structure — measured best) ----------------
#define ROWB 80
#define BUFB (128 * ROWB)
#define STGB (4 * BUFB)
#define BG_SMEM (2 * STGB)

__global__ __launch_bounds__(256, 2)
void bgemm(const bf16* __restrict__ Ahg, const bf16* __restrict__ Alg,
           const bf16* __restrict__ Bhg, const bf16* __restrict__ Blg,
           const float* __restrict__ bias,
           float* __restrict__ Cf, bf16* __restrict__ Ch, bf16* __restrict__ Cl,
           int K, int lda, int ldb, int ldc,
           long long sA, long long sB, long long sC,
           int headmode, int D, int dk, int skip_lh) {
    extern __shared__ char smraw[];
    const uint32_t sb = smem_u32(smraw);

    const int tid = threadIdx.x, lane = tid & 31, wid = tid >> 5;
    const int m_off = (wid >> 2) * 64, n_off = (wid & 3) * 32;
    const int rowBase = blockIdx.y << 7, colBase = blockIdx.x << 7;

    const bf16 *Ah, *Al, *Bh, *Bl;
    size_t coff;
    if (headmode) {
        int bz = blockIdx.z, b = bz >> 3, h = bz & 7;
        size_t off = (size_t)b * 256 * D + (size_t)h * dk;   // D = row stride here
        Ah = Ahg + off; Al = Alg + off; Bh = Bhg + off; Bl = Blg + off;
        coff = (size_t)bz * sC;
    } else {
        Ah = Ahg + (size_t)blockIdx.z * sA; Al = Alg + (size_t)blockIdx.z * sA;
        Bh = Bhg + (size_t)blockIdx.z * sB; Bl = Blg + (size_t)blockIdx.z * sB;
        coff = (size_t)blockIdx.z * sC;
    }

    const int nch = K >> 5;

    auto ldg_half = [&](int ch, int half, uint4* st) {
#pragma unroll
        for (int i = 0; i < 4; ++i) {
            int c = tid + ((half * 4 + i) << 8);
            int buf = c >> 9, idx = c & 511;
            int row = idx >> 2, seg = idx & 3;
            const bf16* g;
            int ld;
            if (buf == 0)      { g = Ah; ld = lda; }
            else if (buf == 1) { g = Al; ld = lda; }
            else if (buf == 2) { g = Bh; ld = ldb; }
            else               { g = Bl; ld = ldb; }
            int grow = ((buf < 2) ? rowBase : colBase) + row;
            st[i] = *(const uint4*)(g + (size_t)grow * ld + (ch << 5) + (seg << 3));
        }
    };
    auto sts_half = [&](int half, int stage, const uint4* st) {
        uint32_t sbase = sb + stage * STGB;
#pragma unroll
        for (int i = 0; i < 4; ++i) {
            int c = tid + ((half * 4 + i) << 8);
            int buf = c >> 9, idx = c & 511;
            int row = idx >> 2, seg = idx & 3;
            sts128(sbase + buf * BUFB + row * ROWB + (seg << 4), st[i]);
        }
    };

    float acc[4][4][4];
#pragma unroll
    for (int a = 0; a < 4; ++a)
#pragma unroll
        for (int b = 0; b < 4; ++b)
#pragma unroll
            for (int c = 0; c < 4; ++c) acc[a][b][c] = 0.f;

    {
        uint4 p[4];
        ldg_half(0, 0, p);
        sts_half(0, 0, p);
        ldg_half(0, 1, p);
        sts_half(1, 0, p);
    }
    __syncthreads();

    uint4 stg[4];
    for (int ch = 0; ch < nch; ++ch) {
        const int st = ch & 1;
        const uint32_t sbase = sb + st * STGB;
        const uint32_t lrow = (uint32_t)(lane & 15) * ROWB + ((lane >> 4) << 4);
        const bool more = (ch + 1 < nch);

        if (more) ldg_half(ch + 1, 0, stg);

#pragma unroll
        for (int ks = 0; ks < 2; ++ks) {
            uint32_t kb = ks << 5;
            uint32_t afr[4][4], bfr[2][4];
            // pass 0: Ah * Bh
#pragma unroll
            for (int mt = 0; mt < 4; ++mt)
                ldsm4(afr[mt], sbase + (uint32_t)(m_off + mt * 16) * ROWB + lrow + kb);
#pragma unroll
            for (int p = 0; p < 2; ++p)
                ldsm4(bfr[p], sbase + 2 * BUFB + (uint32_t)(n_off + p * 16) * ROWB + lrow + kb);
#pragma unroll
            for (int mt = 0; mt < 4; ++mt)
#pragma unroll
                for (int nt = 0; nt < 4; ++nt)
                    mma16816(acc[mt][nt], afr[mt], bfr[nt >> 1][nt & 1], bfr[nt >> 1][(nt & 1) + 2]);
            // pass 1: Ah * Bl
#pragma unroll
            for (int p = 0; p < 2; ++p)
                ldsm4(bfr[p], sbase + 3 * BUFB + (uint32_t)(n_off + p * 16) * ROWB + lrow + kb);
#pragma unroll
            for (int mt = 0; mt < 4; ++mt)
#pragma unroll
                for (int nt = 0; nt < 4; ++nt)
                    mma16816(acc[mt][nt], afr[mt], bfr[nt >> 1][nt & 1], bfr[nt >> 1][(nt & 1) + 2]);
            // pass 2: Al * Bh  (skipped when Al==0 exactly — value-identical)
            if (!skip_lh) {
#pragma unroll
                for (int mt = 0; mt < 4; ++mt)
                    ldsm4(afr[mt], sbase + BUFB + (uint32_t)(m_off + mt * 16) * ROWB + lrow + kb);
#pragma unroll
                for (int p = 0; p < 2; ++p)
                    ldsm4(bfr[p], sbase + 2 * BUFB + (uint32_t)(n_off + p * 16) * ROWB + lrow + kb);
#pragma unroll
                for (int mt = 0; mt < 4; ++mt)
#pragma unroll
                    for (int nt = 0; nt < 4; ++nt)
                        mma16816(acc[mt][nt], afr[mt], bfr[nt >> 1][nt & 1], bfr[nt >> 1][(nt & 1) + 2]);
            }

            if (more) {
                if (ks == 0) {
                    sts_half(0, st ^ 1, stg);
                    ldg_half(ch + 1, 1, stg);
                } else {
                    sts_half(1, st ^ 1, stg);
                }
            }
        }
        __syncthreads();
    }

#pragma unroll
    for (int mt = 0; mt < 4; ++mt) {
#pragma unroll
        for (int nt = 0; nt < 4; ++nt) {
            int col = colBase + n_off + nt * 8 + (lane & 3) * 2;
            float b0 = 0.f, b1 = 0.f;
            if (bias) { b0 = bias[col]; b1 = bias[col + 1]; }
#pragma unroll
            for (int half = 0; half < 2; ++half) {
                int row = rowBase + m_off + mt * 16 + (lane >> 2) + half * 8;
                float v0 = acc[mt][nt][half * 2] + b0;
                float v1 = acc[mt][nt][half * 2 + 1] + b1;
                size_t ci = coff + (size_t)row * ldc + col;
                if (Cf) *(float2*)(Cf + ci) = make_float2(v0, v1);
                if (Ch) {
                    bf16 h0, l0, h1, l1;
                    splitf(v0, h0, l0); splitf(v1, h1, l1);
                    *(__nv_bfloat162*)(Ch + ci) = __nv_bfloat162(h0, h1);
                    *(__nv_bfloat162*)(Cl + ci) = __nv_bfloat162(l0, l1);
                }
            }
        }
    }
}

// ---------------- producers: split fp32 -> bf16 hi/lo ----------------
__global__ void copy_inputs_hl(const float* __restrict__ in, bf16* __restrict__ xh, bf16* __restrict__ xl) {
    int r = blockIdx.x, c = threadIdx.x * 4;
    float4 v = *(const float4*)(in + (size_t)r * INDIM_ + c);
    bf16 h[4], l[4];
    splitf(v.x, h[0], l[0]); splitf(v.y, h[1], l[1]);
    splitf(v.z, h[2], l[2]); splitf(v.w, h[3], l[3]);
    size_t o = (size_t)r * XLD + c;
    *(__nv_bfloat162*)(xh + o) = __nv_bfloat162(h[0], h[1]);
    *(__nv_bfloat162*)(xh + o + 2) = __nv_bfloat162(h[2], h[3]);
    *(__nv_bfloat162*)(xl + o) = __nv_bfloat162(l[0], l[1]);
    *(__nv_bfloat162*)(xl + o + 2) = __nv_bfloat162(l[2], l[3]);
}

__global__ void adjsplit_kernel(const float* __restrict__ adj, bf16* __restrict__ ah, bf16* __restrict__ al) {
    int idx = blockIdx.x * blockDim.x + threadIdx.x;
    float v = adj[idx];
    bf16 h, l;
    splitf(v, h, l);
    ah[idx] = h; al[idx] = l;
}

__global__ void transpose_w_hl(const float* __restrict__ src, bf16* __restrict__ dh,
                               bf16* __restrict__ dl, int K, int N) {
    __shared__ float t[32][33];
    int n0 = blockIdx.x * 32, k0 = blockIdx.y * 32;
    int x = threadIdx.x, y = threadIdx.y;
#pragma unroll
    for (int i = 0; i < 32; i += 8) t[y + i][x] = src[(size_t)(k0 + y + i) * N + n0 + x];
    __syncthreads();
#pragma unroll
    for (int i = 0; i < 32; i += 8) {
        float v = t[x][y + i];
        bf16 h, l;
        splitf(v, h, l);
        size_t o = (size_t)(n0 + y + i) * K + k0 + x;
        dh[o] = h; dl[o] = l;
    }
}

// batched per-b 256x256 transpose of a slice of a wide hi/lo buffer
__global__ void transpose_b64_hl(const bf16* __restrict__ sh, const bf16* __restrict__ sl,
                                 bf16* __restrict__ dh, bf16* __restrict__ dl,
                                 int srcld, int srcoff) {
    __shared__ bf16 th[32][33], tl[32][33];
    size_t zo = (size_t)blockIdx.z * 65536;
    int n0 = blockIdx.x * 32, k0 = blockIdx.y * 32;
    int x = threadIdx.x, y = threadIdx.y;
#pragma unroll
    for (int i = 0; i < 32; i += 8) {
        size_t o = (size_t)(blockIdx.z * 256 + k0 + y + i) * srcld + srcoff + n0 + x;
        th[y + i][x] = sh[o];
        tl[y + i][x] = sl[o];
    }
    __syncthreads();
#pragma unroll
    for (int i = 0; i < 32; i += 8) {
        size_t o = zo + (size_t)(n0 + y + i) * 256 + k0 + x;
        dh[o] = th[x][y + i];
        dl[o] = tl[x][y + i];
    }
}

// concat bias: [qb | kb | zeros]
__global__ void build_biasqk(const float* __restrict__ qb, const float* __restrict__ kb,
                             float* __restrict__ dst, int D, int total) {
    int i = blockIdx.x * blockDim.x + threadIdx.x;
    if (i >= total) return;
    float v = 0.f;
    if (i < D) v = qb[i];
    else if (i < 2 * D) v = kb[i - D];
    dst[i] = v;
}

// ---------------- mask dtype detection + pad extraction ----------------
__global__ void detect_mask_kernel(const unsigned int* __restrict__ w) {
    __shared__ int fl[3];
    if (threadIdx.x < 3) fl[threadIdx.x] = 0;
    __syncthreads();
    int fu8 = 0, ff32 = 0, fbf = 0;
    for (int i = threadIdx.x; i < 1048576; i += blockDim.x) {
        unsigned v = w[i];
        if (v == 0u || v == 1u) continue;
        if (v == 0x3F800000u) { ff32 = 1; continue; }
        unsigned b0 = v & 255u, b1 = (v >> 8) & 255u, b2 = (v >> 16) & 255u, b3 = v >> 24;
        if (b0 < 2u && b1 < 2u && b2 < 2u && b3 < 2u) { fu8 = 1; continue; }
        unsigned h0 = v & 0xFFFFu, h1 = v >> 16;
        if ((h0 == 0u || h0 == 0x3F80u) && (h1 == 0u || h1 == 0x3F80u)) fbf = 1;
    }
    if (fu8)  atomicOr(&fl[0], 1);
    if (ff32) atomicOr(&fl[1], 1);
    if (fbf)  atomicOr(&fl[2], 1);
    __syncthreads();
    if (threadIdx.x == 0) {
        int kind;
        if (fl[2]) kind = 3;
        else if (fl[1]) kind = 2;
        else if (fl[0]) kind = 0;
        else kind = 1;
        g_maskkind = kind;
    }
}
__global__ void extract_pad_kernel(const void* __restrict__ mask, float* __restrict__ pad) {
    int idx = blockIdx.x * blockDim.x + threadIdx.x;
    int b = idx >> 8, i = idx & 255;
    size_t e = (size_t)b * 65536 + (size_t)i * 257;
    int kind = g_maskkind;
    float v;
    if (kind == 0)      v = ((const unsigned char*)mask)[e] ? 1.f : 0.f;
    else if (kind == 1) v = ((const int*)mask)[e] ? 1.f : 0.f;
    else if (kind == 2) v = (((const float*)mask)[e] != 0.f) ? 1.f : 0.f;
    else                v = (((const unsigned short*)mask)[e] != 0) ? 1.f : 0.f;
    pad[idx] = v;
}

// ---------------- elementwise ----------------
__global__ void rowsum_kernel(const float* __restrict__ A, float* __restrict__ denom) {
    int warp = threadIdx.x >> 5, lane = threadIdx.x & 31;
    int row = blockIdx.x * 8 + warp;
    const float4* p = (const float4*)(A + (size_t)row * 256);
    float4 v0 = p[lane], v1 = p[lane + 32];
    float s = v0.x + v0.y + v0.z + v0.w + v1.x + v1.y + v1.z + v1.w;
#pragma unroll
    for (int w = 16; w; w >>= 1) s += __shfl_xor_sync(0xffffffffu, s, w);
    if (lane == 0) denom[row] = s + 1.f;
}

__global__ void combine_hl_kernel(const float* __restrict__ t2,
                                  const bf16* __restrict__ xwh, const bf16* __restrict__ xwl,
                                  const float* __restrict__ bias, const float* __restrict__ denom,
                                  bf16* __restrict__ xh, bf16* __restrict__ xl, int coloff,
                                  float* __restrict__ outf, int xwld, int xwoff) {
    int r = blockIdx.x, c = threadIdx.x;
    float bc = bias[c];
    float d = denom[r];
    size_t si = (size_t)r * 256 + c;
    size_t sx = (size_t)r * xwld + xwoff + c;
    float xw = __bfloat162float(xwh[sx]) + __bfloat162float(xwl[sx]);
    float v = (t2[si] + bc) / d;
    float o = fmaxf(v, 0.f) + xw + bc;
    if (outf) {
        outf[si] = o;
    } else {
        bf16 h, l;
        splitf(o, h, l);
        size_t di = (size_t)r * XLD + coloff + c;
        xh[di] = h; xl[di] = l;
    }
}

// ---------------- fused masked softmax + head sum (batched heads, 2 syncs) ----------------
__global__ __launch_bounds__(256)
void softmax_headsum_kernel(const float* __restrict__ Sc, const float* __restrict__ pad,
                            float* __restrict__ Aout, float scale) {
    int row = blockIdx.x;
    int b = row >> 8, qi = row & 255;
    int j = threadIdx.x;
    __shared__ float redm[64], reds[64];
    int warp = j >> 5, lane = j & 31;
    float padj = pad[b * 256 + j];
    float padq = pad[b * 256 + qi];
    bool valid = (padj == 0.f);
    const float* base = Sc + (((size_t)(b * 8)) << 16) + (size_t)qi * 256 + j;

    float s[8], m[8], e[8];
#pragma unroll
    for (int h = 0; h < 8; ++h) s[h] = base[(size_t)h << 16] * scale;
#pragma unroll
    for (int h = 0; h < 8; ++h) m[h] = valid ? s[h] : -3e38f;
#pragma unroll
    for (int w = 16; w; w >>= 1)
#pragma unroll
        for (int h = 0; h < 8; ++h) m[h] = fmaxf(m[h], __shfl_xor_sync(0xffffffffu, m[h], w));
    if (lane == 0) {
#pragma unroll
        for (int h = 0; h < 8; ++h) redm[h * 8 + warp] = m[h];
    }
    __syncthreads();
    float mx[8];
#pragma unroll
    for (int h = 0; h < 8; ++h) {
        float v = redm[h * 8];
#pragma unroll
        for (int w = 1; w < 8; ++w) v = fmaxf(v, redm[h * 8 + w]);
        mx[h] = v;
    }
#pragma unroll
    for (int h = 0; h < 8; ++h) e[h] = valid ? expf(s[h] - mx[h]) : 0.f;
    float t[8];
#pragma unroll
    for (int h = 0; h < 8; ++h) t[h] = e[h];
#pragma unroll
    for (int w = 16; w; w >>= 1)
#pragma unroll
        for (int h = 0; h < 8; ++h) t[h] += __shfl_xor_sync(0xffffffffu, t[h], w);
    if (lane == 0) {
#pragma unroll
        for (int h = 0; h < 8; ++h) reds[h * 8 + warp] = t[h];
    }
    __syncthreads();
    float acc = 0.f;
#pragma unroll
    for (int h = 0; h < 8; ++h) {
        float se = reds[h * 8];
#pragma unroll
        for (int w = 1; w < 8; ++w) se += reds[h * 8 + w];
        acc += e[h] / se;
    }
    Aout[(size_t)b * 65536 + (size_t)qi * 256 + j] = (padq != 0.f) ? 0.f : acc;
}

// ---------------- exact top-200 threshold (4-pass MSD radix select) ----------------
__global__ __launch_bounds__(1024)
void topk_thresh_kernel(const float* __restrict__ a, float* __restrict__ thr) {
    int b = blockIdx.x;
    const float4* base = (const float4*)(a + (size_t)b * 65536);
    __shared__ unsigned hist[256];
    __shared__ unsigned s_prefix, s_rem, s_zcnt;
    if (threadIdx.x == 0) { s_prefix = 0; s_rem = TOPK_; s_zcnt = 0; }
    __syncthreads();
    for (int pass = 0; pass < 4; ++pass) {
        if (threadIdx.x < 256) hist[threadIdx.x] = 0;
        __syncthreads();
        int shift = 24 - pass * 8;
        unsigned pmask = pass ? (0xFFFFFFFFu << (shift + 8)) : 0u;
        unsigned pref = s_prefix & pmask;
        unsigned lz = 0;
        for (int i = threadIdx.x; i < 16384; i += 1024) {
            float4 v = base[i];
            unsigned kx[4] = {__float_as_uint(v.x), __float_as_uint(v.y),
                              __float_as_uint(v.z), __float_as_uint(v.w)};
#pragma unroll
            for (int t = 0; t < 4; ++t) {
                unsigned key = kx[t];
                if (key == 0u) { if (pass == 0) lz++; }
                else if ((key & pmask) == pref)
                    atomicAdd(&hist[(key >> shift) & 255u], 1u);
            }
        }
        if (pass == 0 && lz) atomicAdd(&s_zcnt, lz);
        __syncthreads();
        if (threadIdx.x == 0) {
            unsigned rem = s_rem, cum = 0;
            int chosen = 0;
            for (int d = 255; d >= 0; --d) {
                unsigned c = hist[d];
                if (d == 0 && ((s_prefix & pmask) == 0u)) c += s_zcnt;
                if (cum + c >= rem) { chosen = d; s_rem = rem - cum; break; }
                cum += c;
            }
            s_prefix |= (unsigned)chosen << shift;
        }
        __syncthreads();
    }
    if (threadIdx.x == 0) thr[b] = __uint_as_float(s_prefix);
}

// ---------------- top-k selection mask + new denom (R9 form) ----------------
__global__ void maskdenom_kernel(const float* __restrict__ a, const float* __restrict__ thr,
                                 bf16* __restrict__ a2h, bf16* __restrict__ a2l,
                                 float* __restrict__ denom) {
    int b = blockIdx.y, i = blockIdx.x, j = threadIdx.x;
    const float* ab = a + (size_t)b * 65536;
    float th = thr[b];
    float va = ab[i * 256 + j];
    float vb = ab[j * 256 + i];
    float m = (i == j) ? 1.f : ((va >= th ? 1.f : 0.f) + (vb >= th ? 1.f : 0.f));
    float o = m * va;
    bf16 h, l;
    splitf(o, h, l);
    size_t oi = (size_t)b * 65536 + i * 256 + j;
    a2h[oi] = h; a2l[oi] = l;
    float s = o;
#pragma unroll
    for (int w = 16; w; w >>= 1) s += __shfl_xor_sync(0xffffffffu, s, w);
    __shared__ float ws[8];
    int warp = threadIdx.x >> 5, lane = threadIdx.x & 31;
    if (lane == 0) ws[warp] = s;
    __syncthreads();
    if (threadIdx.x == 0) {
        float t = 0.f;
#pragma unroll
        for (int w = 0; w < 8; ++w) t += ws[w];
        denom[b * 256 + i] = t + 1.f;
    }
}

// ---------------- host orchestration ----------------
extern "C" void kernel_launch(void* const* d_in, const int* in_sizes, int n_in,
                              void* d_out, int out_size) {
    const float* adj    = (const float*)d_in[0];
    const float* inputs = (const float*)d_in[1];
    const void*  smask  = d_in[2];
    const float* Ww[3]  = {(const float*)d_in[3], (const float*)d_in[5], (const float*)d_in[7]};
    const float* Wb[3]  = {(const float*)d_in[4], (const float*)d_in[6], (const float*)d_in[8]};
    const float* qw[2]  = {(const float*)d_in[9],  (const float*)d_in[13]};
    const float* qb[2]  = {(const float*)d_in[10], (const float*)d_in[14]};
    const float* kw[2]  = {(const float*)d_in[11], (const float*)d_in[15]};
    const float* kb[2]  = {(const float*)d_in[12], (const float*)d_in[16]};
    float* out = (float*)d_out;

    bf16 *xh, *xl, *qkh, *qkl, *a2h, *a2l, *adjh, *adjl;
    bf16 *xwh, *xwl, *xwth, *xwtl, *wth, *wtl;
    float *sc, *a, *t2, *denom, *thr, *pad, *biasqk;
    cudaGetSymbolAddress((void**)&xh, g_xh);    cudaGetSymbolAddress((void**)&xl, g_xl);
    cudaGetSymbolAddress((void**)&qkh, g_qkh);  cudaGetSymbolAddress((void**)&qkl, g_qkl);
    cudaGetSymbolAddress((void**)&a2h, g_a2h);  cudaGetSymbolAddress((void**)&a2l, g_a2l);
    cudaGetSymbolAddress((void**)&adjh, g_adjh); cudaGetSymbolAddress((void**)&adjl, g_adjl);
    cudaGetSymbolAddress((void**)&xwh, g_xwh);  cudaGetSymbolAddress((void**)&xwl, g_xwl);
    cudaGetSymbolAddress((void**)&xwth, g_xwth); cudaGetSymbolAddress((void**)&xwtl, g_xwtl);
    cudaGetSymbolAddress((void**)&wth, g_wth);  cudaGetSymbolAddress((void**)&wtl, g_wtl);
    cudaGetSymbolAddress((void**)&biasqk, g_biasqk);
    cudaGetSymbolAddress((void**)&sc, g_scores);
    cudaGetSymbolAddress((void**)&a, g_a);
    cudaGetSymbolAddress((void**)&t2, g_t2);
    cudaGetSymbolAddress((void**)&denom, g_denom);
    cudaGetSymbolAddress((void**)&thr, g_thr);
    cudaGetSymbolAddress((void**)&pad, g_pad);

    // weight buffer layout: W0T at 0; merged layer-1 [QW0T;KW0T;W1T] rows 0..1791, K=768;
    // merged layer-2 [QW1T;KW1T;W2T] rows 0..2303, K=1024.
    const long long oW0 = 0;
    const long long oM1 = 131072;                    // 1792*768 elems
    const long long oM2 = oM1 + 1792LL * 768;        // 2304*1024 elems
    const long long oM[2] = {oM1, oM2};

    cudaFuncSetAttribute(bgemm, cudaFuncAttributeMaxDynamicSharedMemorySize, BG_SMEM);

    dim3 tb(32, 8);
    // ---- preprocessing (4th launch = representative bgemm, for ncu) ----
    copy_inputs_hl<<<BS_, 128>>>(inputs, xh, xl);                          // 1
    transpose_w_hl<<<dim3(8, 16), tb>>>(Ww[0], wth + oW0, wtl + oW0, 512, 256);  // 2
    detect_mask_kernel<<<1, 256>>>((const unsigned int*)smask);            // 3
    // 4: xw0 = x @ W0 (hi/lo out, no bias)  [PROFILED]
    bgemm<<<dim3(2, 128, 1), 256, BG_SMEM>>>(xh, xl, wth + oW0, wtl + oW0, nullptr,
                                             nullptr, xwh, xwl, 512, XLD, 512, 256,
                                             0, 0, 0, 0, 0, 0, 0);
    extract_pad_kernel<<<64, 256>>>(smask, pad);
    adjsplit_kernel<<<B_ * S_ * S_ / 1024, 1024>>>(adj, adjh, adjl);
    rowsum_kernel<<<BS_ / 8, 256>>>(adj, denom);
    // merged layer-1 weights: rows [QW0T(768) | KW0T(768) | W1T(256)], K=768
    transpose_w_hl<<<dim3(24, 24), tb>>>(qw[0], wth + oM1, wtl + oM1, 768, 768);
    transpose_w_hl<<<dim3(24, 24), tb>>>(kw[0], wth + oM1 + 768LL * 768, wtl + oM1 + 768LL * 768, 768, 768);
    transpose_w_hl<<<dim3(8, 24), tb>>>(Ww[1], wth + oM1 + 1536LL * 768, wtl + oM1 + 1536LL * 768, 768, 256);
    // merged layer-2 weights: rows [QW1T(1024) | KW1T(1024) | W2T(256)], K=1024
    transpose_w_hl<<<dim3(32, 32), tb>>>(qw[1], wth + oM2, wtl + oM2, 1024, 1024);
    transpose_w_hl<<<dim3(32, 32), tb>>>(kw[1], wth + oM2 + 1024LL * 1024, wtl + oM2 + 1024LL * 1024, 1024, 1024);
    transpose_w_hl<<<dim3(8, 32), tb>>>(Ww[2], wth + oM2 + 2048LL * 1024, wtl + oM2 + 2048LL * 1024, 1024, 256);

    // ---- layer 0 ----
    transpose_b64_hl<<<dim3(8, 8, 64), tb>>>(xwh, xwl, xwth, xwtl, 256, 0);
    bgemm<<<dim3(2, 2, 64), 256, BG_SMEM>>>(adjh, adjl, xwth, xwtl, nullptr,
                                            t2, nullptr, nullptr, 256, 256, 256, 256,
                                            65536LL, 65536LL, 65536LL, 0, 0, 0, 1);
    combine_hl_kernel<<<BS_, 256>>>(t2, xwh, xwl, Wb[0], denom, xh, xl, 512, nullptr, 256, 0);

    // ---- layers 1 and 2 ----
    for (int L = 1; L <= 2; ++L) {
        int D = INDIM_ + 256 * L;   // 768, 1024
        int dk = D / HEADS_;        // 96, 128
        int ai = L - 1;
        int NQK = 2 * D + 256;      // 1792, 2304
        build_biasqk<<<(NQK + 255) / 256, 256>>>(qb[ai], kb[ai], biasqk, D, NQK);
        // merged [Q | K | xw] projection (single launch)
        bgemm<<<dim3(NQK / 128, 128, 1), 256, BG_SMEM>>>(xh, xl, wth + oM[ai], wtl + oM[ai], biasqk,
                                                         nullptr, qkh, qkl, D, XLD, D, QKLD,
                                                         0, 0, 0, 0, 0, 0, 0);
        // per-head raw scores: A = Q slice, B = K slice (both in qk buffer, ld=QKLD)
        bgemm<<<dim3(2, 2, B_ * HEADS_), 256, BG_SMEM>>>(qkh, qkl, qkh + D, qkl + D, nullptr,
                                                         sc, nullptr, nullptr, dk, QKLD, QKLD, 256,
                                                         0, 0, 65536LL, 1, QKLD, dk, 0);
        softmax_headsum_kernel<<<BS_, 256>>>(sc, pad, a, 1.0f / sqrtf((float)dk));
        topk_thresh_kernel<<<B_, 1024>>>(a, thr);
        maskdenom_kernel<<<dim3(S_, B_), 256>>>(a, thr, a2h, a2l, denom);
        // xw slice -> transposed scratch, then t2 = a2 @ xw
        transpose_b64_hl<<<dim3(8, 8, 64), tb>>>(qkh, qkl, xwth, xwtl, QKLD, 2 * D);
        bgemm<<<dim3(2, 2, 64), 256, BG_SMEM>>>(a2h, a2l, xwth, xwtl, nullptr,
                                                t2, nullptr, nullptr, 256, 256, 256, 256,
                                                65536LL, 65536LL, 65536LL, 0, 0, 0, 0);
        if (L < 2)
            combine_hl_kernel<<<BS_, 256>>>(t2, qkh, qkl, Wb[L], denom, xh, xl, 512 + 256 * L,
                                            nullptr, QKLD, 2 * D);
        else
            combine_hl_kernel<<<BS_, 256>>>(t2, qkh, qkl, Wb[L], denom, nullptr, nullptr, 0,
                                            out, QKLD, 2 * D);
    }
}

// round 16
// speedup vs baseline: 2.5523x; 2.5523x over previous
#include <cuda_runtime.h>
#include <cuda_bf16.h>
#include <math.h>
#include <stdint.h>

// Problem constants
#define B_      64
#define S_      256
#define INDIM_  512
#define MEM_    256
#define HEADS_  8
#define TOPK_   200
#define XLD     1024
#define BS_     (B_ * S_)

typedef __nv_bfloat16 bf16;

// ---------------- static device scratch (no allocations allowed) ----------------
__device__ bf16  g_xh[BS_ * XLD];
__device__ bf16  g_xl[BS_ * XLD];
__device__ bf16  g_qh[BS_ * XLD];
__device__ bf16  g_ql[BS_ * XLD];
__device__ bf16  g_kh[BS_ * XLD];
__device__ bf16  g_kl[BS_ * XLD];
__device__ bf16  g_a2h[B_ * S_ * S_];
__device__ bf16  g_a2l[B_ * S_ * S_];
__device__ bf16  g_adjh[B_ * S_ * S_];
__device__ bf16  g_adjl[B_ * S_ * S_];
__device__ bf16  g_xwh[BS_ * MEM_];
__device__ bf16  g_xwl[BS_ * MEM_];
__device__ bf16  g_xwth[BS_ * MEM_];
__device__ bf16  g_xwtl[BS_ * MEM_];
__device__ bf16  g_wth[4 * 1024 * 1024];
__device__ bf16  g_wtl[4 * 1024 * 1024];
__device__ float g_scores[B_ * HEADS_ * S_ * S_];
__device__ float g_a[B_ * S_ * S_];
__device__ float g_t2[BS_ * MEM_];
__device__ float g_denom[BS_];
__device__ float g_thr[B_];
__device__ float g_pad[BS_];
__device__ int   g_maskflags[3];   // [0]=u8, [1]=f32, [2]=bf16

// ---------------- small helpers ----------------
__device__ __forceinline__ uint32_t smem_u32(const void* p) {
    uint32_t a;
    asm("{ .reg .u64 t; cvta.to.shared.u64 t, %1; cvt.u32.u64 %0, t; }" : "=r"(a) : "l"(p));
    return a;
}
__device__ __forceinline__ void ldsm4(uint32_t* r, uint32_t addr) {
    asm volatile("ldmatrix.sync.aligned.m8n8.x4.shared.b16 {%0,%1,%2,%3}, [%4];"
                 : "=r"(r[0]), "=r"(r[1]), "=r"(r[2]), "=r"(r[3]) : "r"(addr));
}
__device__ __forceinline__ void sts128(uint32_t addr, uint4 v) {
    asm volatile("st.shared.v4.b32 [%0], {%1,%2,%3,%4};"
                 :: "r"(addr), "r"(v.x), "r"(v.y), "r"(v.z), "r"(v.w) : "memory");
}
__device__ __forceinline__ void mma16816(float* d, const uint32_t* a, uint32_t b0, uint32_t b1) {
    asm volatile("mma.sync.aligned.m16n8k16.row.col.f32.bf16.bf16.f32 "
                 "{%0,%1,%2,%3}, {%4,%5,%6,%7}, {%8,%9}, {%0,%1,%2,%3};"
                 : "+f"(d[0]), "+f"(d[1]), "+f"(d[2]), "+f"(d[3])
                 : "r"(a[0]), "r"(a[1]), "r"(a[2]), "r"(a[3]), "r"(b0), "r"(b1));
}
__device__ __forceinline__ void splitf(float v, bf16& h, bf16& l) {
    h = __float2bfloat16(v);
    l = __float2bfloat16(v - __bfloat162float(h));
}

// ---------------- bf16-split tensor-core GEMM (R8 structure — measured best) ----------------
// C[M,N] = (Ah+Al)[M,K] @ (Bh+Bl)[N,K]^T, fp32 accum; 3 passes per k16: hh, hl, lh.
// skip_lh=1: A known exact in bf16 (Al==0) -> lh pass adds exact zeros -> skip (value-identical).
#define ROWB 80
#define BUFB (128 * ROWB)
#define STGB (4 * BUFB)
#define BG_SMEM (2 * STGB)

__global__ __launch_bounds__(256, 2)
void bgemm(const bf16* __restrict__ Ahg, const bf16* __restrict__ Alg,
           const bf16* __restrict__ Bhg, const bf16* __restrict__ Blg,
           const float* __restrict__ bias,
           float* __restrict__ Cf, bf16* __restrict__ Ch, bf16* __restrict__ Cl,
           int K, int lda, int ldb, int ldc,
           long long sA, long long sB, long long sC,
           int headmode, int D, int dk, int skip_lh) {
    extern __shared__ char smraw[];
    const uint32_t sb = smem_u32(smraw);

    const int tid = threadIdx.x, lane = tid & 31, wid = tid >> 5;
    const int m_off = (wid >> 2) * 64, n_off = (wid & 3) * 32;
    const int rowBase = blockIdx.y << 7, colBase = blockIdx.x << 7;

    const bf16 *Ah, *Al, *Bh, *Bl;
    size_t coff;
    if (headmode) {
        int bz = blockIdx.z, b = bz >> 3, h = bz & 7;
        size_t off = (size_t)b * 256 * D + (size_t)h * dk;
        Ah = Ahg + off; Al = Alg + off; Bh = Bhg + off; Bl = Blg + off;
        coff = (size_t)bz * sC;
    } else {
        Ah = Ahg + (size_t)blockIdx.z * sA; Al = Alg + (size_t)blockIdx.z * sA;
        Bh = Bhg + (size_t)blockIdx.z * sB; Bl = Blg + (size_t)blockIdx.z * sB;
        coff = (size_t)blockIdx.z * sC;
    }

    const int nch = K >> 5;

    auto ldg_half = [&](int ch, int half, uint4* st) {
#pragma unroll
        for (int i = 0; i < 4; ++i) {
            int c = tid + ((half * 4 + i) << 8);
            int buf = c >> 9, idx = c & 511;
            int row = idx >> 2, seg = idx & 3;
            const bf16* g;
            int ld;
            if (buf == 0)      { g = Ah; ld = lda; }
            else if (buf == 1) { g = Al; ld = lda; }
            else if (buf == 2) { g = Bh; ld = ldb; }
            else               { g = Bl; ld = ldb; }
            int grow = ((buf < 2) ? rowBase : colBase) + row;
            st[i] = *(const uint4*)(g + (size_t)grow * ld + (ch << 5) + (seg << 3));
        }
    };
    auto sts_half = [&](int half, int stage, const uint4* st) {
        uint32_t sbase = sb + stage * STGB;
#pragma unroll
        for (int i = 0; i < 4; ++i) {
            int c = tid + ((half * 4 + i) << 8);
            int buf = c >> 9, idx = c & 511;
            int row = idx >> 2, seg = idx & 3;
            sts128(sbase + buf * BUFB + row * ROWB + (seg << 4), st[i]);
        }
    };

    float acc[4][4][4];
#pragma unroll
    for (int a = 0; a < 4; ++a)
#pragma unroll
        for (int b = 0; b < 4; ++b)
#pragma unroll
            for (int c = 0; c < 4; ++c) acc[a][b][c] = 0.f;

    {
        uint4 p[4];
        ldg_half(0, 0, p);
        sts_half(0, 0, p);
        ldg_half(0, 1, p);
        sts_half(1, 0, p);
    }
    __syncthreads();

    uint4 stg[4];
    for (int ch = 0; ch < nch; ++ch) {
        const int st = ch & 1;
        const uint32_t sbase = sb + st * STGB;
        const uint32_t lrow = (uint32_t)(lane & 15) * ROWB + ((lane >> 4) << 4);
        const bool more = (ch + 1 < nch);

        if (more) ldg_half(ch + 1, 0, stg);

#pragma unroll
        for (int ks = 0; ks < 2; ++ks) {
            uint32_t kb = ks << 5;
            uint32_t afr[4][4], bfr[2][4];
            // pass 0: Ah * Bh
#pragma unroll
            for (int mt = 0; mt < 4; ++mt)
                ldsm4(afr[mt], sbase + (uint32_t)(m_off + mt * 16) * ROWB + lrow + kb);
#pragma unroll
            for (int p = 0; p < 2; ++p)
                ldsm4(bfr[p], sbase + 2 * BUFB + (uint32_t)(n_off + p * 16) * ROWB + lrow + kb);
#pragma unroll
            for (int mt = 0; mt < 4; ++mt)
#pragma unroll
                for (int nt = 0; nt < 4; ++nt)
                    mma16816(acc[mt][nt], afr[mt], bfr[nt >> 1][nt & 1], bfr[nt >> 1][(nt & 1) + 2]);
            // pass 1: Ah * Bl
#pragma unroll
            for (int p = 0; p < 2; ++p)
                ldsm4(bfr[p], sbase + 3 * BUFB + (uint32_t)(n_off + p * 16) * ROWB + lrow + kb);
#pragma unroll
            for (int mt = 0; mt < 4; ++mt)
#pragma unroll
                for (int nt = 0; nt < 4; ++nt)
                    mma16816(acc[mt][nt], afr[mt], bfr[nt >> 1][nt & 1], bfr[nt >> 1][(nt & 1) + 2]);
            // pass 2: Al * Bh  (skipped when Al==0 exactly — value-identical)
            if (!skip_lh) {
#pragma unroll
                for (int mt = 0; mt < 4; ++mt)
                    ldsm4(afr[mt], sbase + BUFB + (uint32_t)(m_off + mt * 16) * ROWB + lrow + kb);
#pragma unroll
                for (int p = 0; p < 2; ++p)
                    ldsm4(bfr[p], sbase + 2 * BUFB + (uint32_t)(n_off + p * 16) * ROWB + lrow + kb);
#pragma unroll
                for (int mt = 0; mt < 4; ++mt)
#pragma unroll
                    for (int nt = 0; nt < 4; ++nt)
                        mma16816(acc[mt][nt], afr[mt], bfr[nt >> 1][nt & 1], bfr[nt >> 1][(nt & 1) + 2]);
            }

            if (more) {
                if (ks == 0) {
                    sts_half(0, st ^ 1, stg);
                    ldg_half(ch + 1, 1, stg);
                } else {
                    sts_half(1, st ^ 1, stg);
                }
            }
        }
        __syncthreads();
    }

#pragma unroll
    for (int mt = 0; mt < 4; ++mt) {
#pragma unroll
        for (int nt = 0; nt < 4; ++nt) {
            int col = colBase + n_off + nt * 8 + (lane & 3) * 2;
            float b0 = 0.f, b1 = 0.f;
            if (bias) { b0 = bias[col]; b1 = bias[col + 1]; }
#pragma unroll
            for (int half = 0; half < 2; ++half) {
                int row = rowBase + m_off + mt * 16 + (lane >> 2) + half * 8;
                float v0 = acc[mt][nt][half * 2] + b0;
                float v1 = acc[mt][nt][half * 2 + 1] + b1;
                size_t ci = coff + (size_t)row * ldc + col;
                if (Cf) *(float2*)(Cf + ci) = make_float2(v0, v1);
                if (Ch) {
                    bf16 h0, l0, h1, l1;
                    splitf(v0, h0, l0); splitf(v1, h1, l1);
                    *(__nv_bfloat162*)(Ch + ci) = __nv_bfloat162(h0, h1);
                    *(__nv_bfloat162*)(Cl + ci) = __nv_bfloat162(l0, l1);
                }
            }
        }
    }
}

// ---------------- producers: split fp32 -> bf16 hi/lo ----------------
__global__ void copy_inputs_hl(const float* __restrict__ in, bf16* __restrict__ xh, bf16* __restrict__ xl) {
    int r = blockIdx.x, c = threadIdx.x * 4;
    float4 v = *(const float4*)(in + (size_t)r * INDIM_ + c);
    bf16 h[4], l[4];
    splitf(v.x, h[0], l[0]); splitf(v.y, h[1], l[1]);
    splitf(v.z, h[2], l[2]); splitf(v.w, h[3], l[3]);
    size_t o = (size_t)r * XLD + c;
    *(__nv_bfloat162*)(xh + o) = __nv_bfloat162(h[0], h[1]);
    *(__nv_bfloat162*)(xh + o + 2) = __nv_bfloat162(h[2], h[3]);
    *(__nv_bfloat162*)(xl + o) = __nv_bfloat162(l[0], l[1]);
    *(__nv_bfloat162*)(xl + o + 2) = __nv_bfloat162(l[2], l[3]);
}

__global__ void adjsplit_kernel(const float* __restrict__ adj, bf16* __restrict__ ah, bf16* __restrict__ al) {
    int idx = blockIdx.x * blockDim.x + threadIdx.x;
    float v = adj[idx];
    bf16 h, l;
    splitf(v, h, l);
    ah[idx] = h; al[idx] = l;
}

__global__ void transpose_w_hl(const float* __restrict__ src, bf16* __restrict__ dh,
                               bf16* __restrict__ dl, int K, int N) {
    __shared__ float t[32][33];
    int n0 = blockIdx.x * 32, k0 = blockIdx.y * 32;
    int x = threadIdx.x, y = threadIdx.y;
#pragma unroll
    for (int i = 0; i < 32; i += 8) t[y + i][x] = src[(size_t)(k0 + y + i) * N + n0 + x];
    __syncthreads();
#pragma unroll
    for (int i = 0; i < 32; i += 8) {
        float v = t[x][y + i];
        bf16 h, l;
        splitf(v, h, l);
        size_t o = (size_t)(n0 + y + i) * K + k0 + x;
        dh[o] = h; dl[o] = l;
    }
}

__global__ void transpose_b64_hl(const bf16* __restrict__ sh, const bf16* __restrict__ sl,
                                 bf16* __restrict__ dh, bf16* __restrict__ dl) {
    __shared__ bf16 th[32][33], tl[32][33];
    size_t zo = (size_t)blockIdx.z * 65536;
    int n0 = blockIdx.x * 32, k0 = blockIdx.y * 32;
    int x = threadIdx.x, y = threadIdx.y;
#pragma unroll
    for (int i = 0; i < 32; i += 8) {
        size_t o = zo + (size_t)(k0 + y + i) * 256 + n0 + x;
        th[y + i][x] = sh[o];
        tl[y + i][x] = sl[o];
    }
    __syncthreads();
#pragma unroll
    for (int i = 0; i < 32; i += 8) {
        size_t o = zo + (size_t)(n0 + y + i) * 256 + k0 + x;
        dh[o] = th[x][y + i];
        dl[o] = tl[x][y + i];
    }
}

// ---------------- mask dtype detection (parallel) + pad extraction ----------------
__global__ void reset_flags_kernel() {
    if (threadIdx.x < 3) g_maskflags[threadIdx.x] = 0;
}
// 256 blocks x grid-stride; atomicOr into global flags (idempotent -> deterministic)
__global__ void detect_mask_kernel(const unsigned int* __restrict__ w) {
    int fu8 = 0, ff32 = 0, fbf = 0;
    for (int i = blockIdx.x * blockDim.x + threadIdx.x; i < 1048576; i += gridDim.x * blockDim.x) {
        unsigned v = w[i];
        if (v == 0u || v == 1u) continue;
        if (v == 0x3F800000u) { ff32 = 1; continue; }
        unsigned b0 = v & 255u, b1 = (v >> 8) & 255u, b2 = (v >> 16) & 255u, b3 = v >> 24;
        if (b0 < 2u && b1 < 2u && b2 < 2u && b3 < 2u) { fu8 = 1; continue; }
        unsigned h0 = v & 0xFFFFu, h1 = v >> 16;
        if ((h0 == 0u || h0 == 0x3F80u) && (h1 == 0u || h1 == 0x3F80u)) fbf = 1;
    }
    if (fu8)  atomicOr(&g_maskflags[0], 1);
    if (ff32) atomicOr(&g_maskflags[1], 1);
    if (fbf)  atomicOr(&g_maskflags[2], 1);
}
__global__ void extract_pad_kernel(const void* __restrict__ mask, float* __restrict__ pad) {
    int idx = blockIdx.x * blockDim.x + threadIdx.x;
    int b = idx >> 8, i = idx & 255;
    size_t e = (size_t)b * 65536 + (size_t)i * 257;
    int kind;   // same priority order as before: bf16 > f32 > u8 > i32
    if (g_maskflags[2]) kind = 3;
    else if (g_maskflags[1]) kind = 2;
    else if (g_maskflags[0]) kind = 0;
    else kind = 1;
    float v;
    if (kind == 0)      v = ((const unsigned char*)mask)[e] ? 1.f : 0.f;
    else if (kind == 1) v = ((const int*)mask)[e] ? 1.f : 0.f;
    else if (kind == 2) v = (((const float*)mask)[e] != 0.f) ? 1.f : 0.f;
    else                v = (((const unsigned short*)mask)[e] != 0) ? 1.f : 0.f;
    pad[idx] = v;
}

// ---------------- elementwise ----------------
__global__ void rowsum_kernel(const float* __restrict__ A, float* __restrict__ denom) {
    int warp = threadIdx.x >> 5, lane = threadIdx.x & 31;
    int row = blockIdx.x * 8 + warp;
    const float4* p = (const float4*)(A + (size_t)row * 256);
    float4 v0 = p[lane], v1 = p[lane + 32];
    float s = v0.x + v0.y + v0.z + v0.w + v1.x + v1.y + v1.z + v1.w;
#pragma unroll
    for (int w = 16; w; w >>= 1) s += __shfl_xor_sync(0xffffffffu, s, w);
    if (lane == 0) denom[row] = s + 1.f;
}

__global__ void combine_hl_kernel(const float* __restrict__ t2,
                                  const bf16* __restrict__ xwh, const bf16* __restrict__ xwl,
                                  const float* __restrict__ bias, const float* __restrict__ denom,
                                  bf16* __restrict__ xh, bf16* __restrict__ xl, int coloff,
                                  float* __restrict__ outf) {
    int r = blockIdx.x, c = threadIdx.x;
    float bc = bias[c];
    float d = denom[r];
    size_t si = (size_t)r * 256 + c;
    float xw = __bfloat162float(xwh[si]) + __bfloat162float(xwl[si]);
    float v = (t2[si] + bc) / d;
    float o = fmaxf(v, 0.f) + xw + bc;
    if (outf) {
        outf[si] = o;
    } else {
        bf16 h, l;
        splitf(o, h, l);
        size_t di = (size_t)r * XLD + coloff + c;
        xh[di] = h; xl[di] = l;
    }
}

// ---------------- fused masked softmax + head sum (batched heads, 2 syncs) ----------------
__global__ __launch_bounds__(256)
void softmax_headsum_kernel(const float* __restrict__ Sc, const float* __restrict__ pad,
                            float* __restrict__ Aout, float scale) {
    int row = blockIdx.x;
    int b = row >> 8, qi = row & 255;
    int j = threadIdx.x;
    __shared__ float redm[64], reds[64];
    int warp = j >> 5, lane = j & 31;
    float padj = pad[b * 256 + j];
    float padq = pad[b * 256 + qi];
    bool valid = (padj == 0.f);
    const float* base = Sc + (((size_t)(b * 8)) << 16) + (size_t)qi * 256 + j;

    float s[8], m[8], e[8];
#pragma unroll
    for (int h = 0; h < 8; ++h) s[h] = base[(size_t)h << 16] * scale;
#pragma unroll
    for (int h = 0; h < 8; ++h) m[h] = valid ? s[h] : -3e38f;
#pragma unroll
    for (int w = 16; w; w >>= 1)
#pragma unroll
        for (int h = 0; h < 8; ++h) m[h] = fmaxf(m[h], __shfl_xor_sync(0xffffffffu, m[h], w));
    if (lane == 0) {
#pragma unroll
        for (int h = 0; h < 8; ++h) redm[h * 8 + warp] = m[h];
    }
    __syncthreads();
    float mx[8];
#pragma unroll
    for (int h = 0; h < 8; ++h) {
        float v = redm[h * 8];
#pragma unroll
        for (int w = 1; w < 8; ++w) v = fmaxf(v, redm[h * 8 + w]);
        mx[h] = v;
    }
#pragma unroll
    for (int h = 0; h < 8; ++h) e[h] = valid ? expf(s[h] - mx[h]) : 0.f;
    float t[8];
#pragma unroll
    for (int h = 0; h < 8; ++h) t[h] = e[h];
#pragma unroll
    for (int w = 16; w; w >>= 1)
#pragma unroll
        for (int h = 0; h < 8; ++h) t[h] += __shfl_xor_sync(0xffffffffu, t[h], w);
    if (lane == 0) {
#pragma unroll
        for (int h = 0; h < 8; ++h) reds[h * 8 + warp] = t[h];
    }
    __syncthreads();
    float acc = 0.f;
#pragma unroll
    for (int h = 0; h < 8; ++h) {
        float se = reds[h * 8];
#pragma unroll
        for (int w = 1; w < 8; ++w) se += reds[h * 8 + w];
        acc += e[h] / se;
    }
    Aout[(size_t)b * 65536 + (size_t)qi * 256 + j] = (padq != 0.f) ? 0.f : acc;
}

// ---------------- exact top-200 threshold (4-pass MSD radix select, R9 form) ----------------
__global__ __launch_bounds__(1024)
void topk_thresh_kernel(const float* __restrict__ a, float* __restrict__ thr) {
    int b = blockIdx.x;
    const float4* base = (const float4*)(a + (size_t)b * 65536);
    __shared__ unsigned hist[256];
    __shared__ unsigned s_prefix, s_rem, s_zcnt;
    if (threadIdx.x == 0) { s_prefix = 0; s_rem = TOPK_; s_zcnt = 0; }
    __syncthreads();
    for (int pass = 0; pass < 4; ++pass) {
        if (threadIdx.x < 256) hist[threadIdx.x] = 0;
        __syncthreads();
        int shift = 24 - pass * 8;
        unsigned pmask = pass ? (0xFFFFFFFFu << (shift + 8)) : 0u;
        unsigned pref = s_prefix & pmask;
        unsigned lz = 0;
        for (int i = threadIdx.x; i < 16384; i += 1024) {
            float4 v = base[i];
            unsigned kx[4] = {__float_as_uint(v.x), __float_as_uint(v.y),
                              __float_as_uint(v.z), __float_as_uint(v.w)};
#pragma unroll
            for (int t = 0; t < 4; ++t) {
                unsigned key = kx[t];
                if (key == 0u) { if (pass == 0) lz++; }
                else if ((key & pmask) == pref)
                    atomicAdd(&hist[(key >> shift) & 255u], 1u);
            }
        }
        if (pass == 0 && lz) atomicAdd(&s_zcnt, lz);
        __syncthreads();
        if (threadIdx.x == 0) {
            unsigned rem = s_rem, cum = 0;
            int chosen = 0;
            for (int d = 255; d >= 0; --d) {
                unsigned c = hist[d];
                if (d == 0 && ((s_prefix & pmask) == 0u)) c += s_zcnt;
                if (cum + c >= rem) { chosen = d; s_rem = rem - cum; break; }
                cum += c;
            }
            s_prefix |= (unsigned)chosen << shift;
        }
        __syncthreads();
    }
    if (threadIdx.x == 0) thr[b] = __uint_as_float(s_prefix);
}

// ---------------- top-k selection mask + new denom (R9 form, writes a2 hi/lo) ----------------
__global__ void maskdenom_kernel(const float* __restrict__ a, const float* __restrict__ thr,
                                 bf16* __restrict__ a2h, bf16* __restrict__ a2l,
                                 float* __restrict__ denom) {
    int b = blockIdx.y, i = blockIdx.x, j = threadIdx.x;
    const float* ab = a + (size_t)b * 65536;
    float th = thr[b];
    float va = ab[i * 256 + j];
    float vb = ab[j * 256 + i];
    float m = (i == j) ? 1.f : ((va >= th ? 1.f : 0.f) + (vb >= th ? 1.f : 0.f));
    float o = m * va;
    bf16 h, l;
    splitf(o, h, l);
    size_t oi = (size_t)b * 65536 + i * 256 + j;
    a2h[oi] = h; a2l[oi] = l;
    float s = o;
#pragma unroll
    for (int w = 16; w; w >>= 1) s += __shfl_xor_sync(0xffffffffu, s, w);
    __shared__ float ws[8];
    int warp = threadIdx.x >> 5, lane = threadIdx.x & 31;
    if (lane == 0) ws[warp] = s;
    __syncthreads();
    if (threadIdx.x == 0) {
        float t = 0.f;
#pragma unroll
        for (int w = 0; w < 8; ++w) t += ws[w];
        denom[b * 256 + i] = t + 1.f;
    }
}

// ---------------- host orchestration ----------------
extern "C" void kernel_launch(void* const* d_in, const int* in_sizes, int n_in,
                              void* d_out, int out_size) {
    const float* adj    = (const float*)d_in[0];
    const float* inputs = (const float*)d_in[1];
    const void*  smask  = d_in[2];
    const float* Ww[3]  = {(const float*)d_in[3], (const float*)d_in[5], (const float*)d_in[7]};
    const float* Wb[3]  = {(const float*)d_in[4], (const float*)d_in[6], (const float*)d_in[8]};
    const float* qw[2]  = {(const float*)d_in[9],  (const float*)d_in[13]};
    const float* qb[2]  = {(const float*)d_in[10], (const float*)d_in[14]};
    const float* kw[2]  = {(const float*)d_in[11], (const float*)d_in[15]};
    const float* kb[2]  = {(const float*)d_in[12], (const float*)d_in[16]};
    float* out = (float*)d_out;

    bf16 *xh, *xl, *qh, *ql, *kh, *kl, *a2h, *a2l, *adjh, *adjl;
    bf16 *xwh, *xwl, *xwth, *xwtl, *wth, *wtl;
    float *sc, *a, *t2, *denom, *thr, *pad;
    cudaGetSymbolAddress((void**)&xh, g_xh);    cudaGetSymbolAddress((void**)&xl, g_xl);
    cudaGetSymbolAddress((void**)&qh, g_qh);    cudaGetSymbolAddress((void**)&ql, g_ql);
    cudaGetSymbolAddress((void**)&kh, g_kh);    cudaGetSymbolAddress((void**)&kl, g_kl);
    cudaGetSymbolAddress((void**)&a2h, g_a2h);  cudaGetSymbolAddress((void**)&a2l, g_a2l);
    cudaGetSymbolAddress((void**)&adjh, g_adjh); cudaGetSymbolAddress((void**)&adjl, g_adjl);
    cudaGetSymbolAddress((void**)&xwh, g_xwh);  cudaGetSymbolAddress((void**)&xwl, g_xwl);
    cudaGetSymbolAddress((void**)&xwth, g_xwth); cudaGetSymbolAddress((void**)&xwtl, g_xwtl);
    cudaGetSymbolAddress((void**)&wth, g_wth);  cudaGetSymbolAddress((void**)&wtl, g_wtl);
    cudaGetSymbolAddress((void**)&sc, g_scores);
    cudaGetSymbolAddress((void**)&a, g_a);
    cudaGetSymbolAddress((void**)&t2, g_t2);
    cudaGetSymbolAddress((void**)&denom, g_denom);
    cudaGetSymbolAddress((void**)&thr, g_thr);
    cudaGetSymbolAddress((void**)&pad, g_pad);

    const long long oW0 = 0, oW1 = 131072, oW2 = 327680;
    const long long oQ0 = 589824, oK0 = 1179648, oQ1 = 1769472, oK1 = 2818048;

    cudaFuncSetAttribute(bgemm, cudaFuncAttributeMaxDynamicSharedMemorySize, BG_SMEM);

    dim3 tb(32, 8);
    // ---- preprocessing (4th launch = representative bgemm, for ncu) ----
    copy_inputs_hl<<<BS_, 128>>>(inputs, xh, xl);                          // 1
    reset_flags_kernel<<<1, 32>>>();                                       // 2
    transpose_w_hl<<<dim3(8, 16), tb>>>(Ww[0], wth + oW0, wtl + oW0, 512, 256);  // 3
    // 4: xw = x @ W0 (hi/lo out, no bias)  [PROFILED]
    bgemm<<<dim3(2, 128, 1), 256, BG_SMEM>>>(xh, xl, wth + oW0, wtl + oW0, nullptr,
                                             nullptr, xwh, xwl, 512, XLD, 512, 256,
                                             0, 0, 0, 0, 0, 0, 0);
    detect_mask_kernel<<<256, 256>>>((const unsigned int*)smask);
    extract_pad_kernel<<<64, 256>>>(smask, pad);
    adjsplit_kernel<<<B_ * S_ * S_ / 1024, 1024>>>(adj, adjh, adjl);
    rowsum_kernel<<<BS_ / 8, 256>>>(adj, denom);
    transpose_w_hl<<<dim3(8, 24), tb>>>(Ww[1], wth + oW1, wtl + oW1, 768, 256);
    transpose_w_hl<<<dim3(8, 32), tb>>>(Ww[2], wth + oW2, wtl + oW2, 1024, 256);
    transpose_w_hl<<<dim3(24, 24), tb>>>(qw[0], wth + oQ0, wtl + oQ0, 768, 768);
    transpose_w_hl<<<dim3(24, 24), tb>>>(kw[0], wth + oK0, wtl + oK0, 768, 768);
    transpose_w_hl<<<dim3(32, 32), tb>>>(qw[1], wth + oQ1, wtl + oQ1, 1024, 1024);
    transpose_w_hl<<<dim3(32, 32), tb>>>(kw[1], wth + oK1, wtl + oK1, 1024, 1024);

    const long long oWT[3] = {oW0, oW1, oW2};
    const long long oQT[2] = {oQ0, oQ1};
    const long long oKT[2] = {oK0, oK1};

    // ---- layer 0 ----
    transpose_b64_hl<<<dim3(8, 8, 64), tb>>>(xwh, xwl, xwth, xwtl);
    // t2 = adj @ xw: adj exact in bf16 -> skip lh pass (value-identical)
    bgemm<<<dim3(2, 2, 64), 256, BG_SMEM>>>(adjh, adjl, xwth, xwtl, nullptr,
                                            t2, nullptr, nullptr, 256, 256, 256, 256,
                                            65536LL, 65536LL, 65536LL, 0, 0, 0, 1);
    combine_hl_kernel<<<BS_, 256>>>(t2, xwh, xwl, Wb[0], denom, xh, xl, 512, nullptr);

    // ---- layers 1 and 2 ----
    for (int L = 1; L <= 2; ++L) {
        int D = INDIM_ + 256 * L;   // 768, 1024
        int dk = D / HEADS_;        // 96, 128
        int ai = L - 1;
        bgemm<<<dim3(D / 128, 128, 1), 256, BG_SMEM>>>(xh, xl, wth + oQT[ai], wtl + oQT[ai], qb[ai],
                                                       nullptr, qh, ql, D, XLD, D, D,
                                                       0, 0, 0, 0, 0, 0, 0);
        bgemm<<<dim3(D / 128, 128, 1), 256, BG_SMEM>>>(xh, xl, wth + oKT[ai], wtl + oKT[ai], kb[ai],
                                                       nullptr, kh, kl, D, XLD, D, D,
                                                       0, 0, 0, 0, 0, 0, 0);
        bgemm<<<dim3(2, 2, B_ * HEADS_), 256, BG_SMEM>>>(qh, ql, kh, kl, nullptr,
                                                         sc, nullptr, nullptr, dk, D, D, 256,
                                                         0, 0, 65536LL, 1, D, dk, 0);
        softmax_headsum_kernel<<<BS_, 256>>>(sc, pad, a, 1.0f / sqrtf((float)dk));
        topk_thresh_kernel<<<B_, 1024>>>(a, thr);
        maskdenom_kernel<<<dim3(S_, B_), 256>>>(a, thr, a2h, a2l, denom);
        bgemm<<<dim3(2, 128, 1), 256, BG_SMEM>>>(xh, xl, wth + oWT[L], wtl + oWT[L], nullptr,
                                                 nullptr, xwh, xwl, D, XLD, D, 256,
                                                 0, 0, 0, 0, 0, 0, 0);
        transpose_b64_hl<<<dim3(8, 8, 64), tb>>>(xwh, xwl, xwth, xwtl);
        bgemm<<<dim3(2, 2, 64), 256, BG_SMEM>>>(a2h, a2l, xwth, xwtl, nullptr,
                                                t2, nullptr, nullptr, 256, 256, 256, 256,
                                                65536LL, 65536LL, 65536LL, 0, 0, 0, 0);
        if (L < 2)
            combine_hl_kernel<<<BS_, 256>>>(t2, xwh, xwl, Wb[L], denom, xh, xl, 512 + 256 * L, nullptr);
        else
            combine_hl_kernel<<<BS_, 256>>>(t2, xwh, xwl, Wb[L], denom, nullptr, nullptr, 0, out);
    }
}

// round 17
// speedup vs baseline: 2.6389x; 1.0339x over previous
#include <cuda_runtime.h>
#include <cuda_bf16.h>
#include <math.h>
#include <stdint.h>

// Problem constants
#define B_      64
#define S_      256
#define INDIM_  512
#define MEM_    256
#define HEADS_  8
#define TOPK_   200
#define XLD     1024
#define BS_     (B_ * S_)

typedef __nv_bfloat16 bf16;

// ---------------- static device scratch (no allocations allowed) ----------------
__device__ bf16  g_xh[BS_ * XLD];
__device__ bf16  g_xl[BS_ * XLD];
__device__ bf16  g_qh[BS_ * XLD];
__device__ bf16  g_ql[BS_ * XLD];
__device__ bf16  g_kh[BS_ * XLD];
__device__ bf16  g_kl[BS_ * XLD];
__device__ bf16  g_a2h[B_ * S_ * S_];
__device__ bf16  g_a2l[B_ * S_ * S_];
__device__ bf16  g_adjh[B_ * S_ * S_];
__device__ bf16  g_adjl[B_ * S_ * S_];
__device__ bf16  g_xwh[BS_ * MEM_];
__device__ bf16  g_xwl[BS_ * MEM_];
__device__ bf16  g_xwth[BS_ * MEM_];
__device__ bf16  g_xwtl[BS_ * MEM_];
__device__ bf16  g_wth[4 * 1024 * 1024];
__device__ bf16  g_wtl[4 * 1024 * 1024];
__device__ float g_scores[B_ * HEADS_ * S_ * S_];
__device__ float g_a[B_ * S_ * S_];
__device__ float g_t2[BS_ * MEM_];
__device__ float g_denom[BS_];
__device__ float g_thr[B_];
__device__ float g_pad[BS_];
__device__ int   g_maskflags[3];   // [0]=u8, [1]=f32, [2]=bf16

// ---------------- small helpers ----------------
__device__ __forceinline__ uint32_t smem_u32(const void* p) {
    uint32_t a;
    asm("{ .reg .u64 t; cvta.to.shared.u64 t, %1; cvt.u32.u64 %0, t; }" : "=r"(a) : "l"(p));
    return a;
}
__device__ __forceinline__ void ldsm4(uint32_t* r, uint32_t addr) {
    asm volatile("ldmatrix.sync.aligned.m8n8.x4.shared.b16 {%0,%1,%2,%3}, [%4];"
                 : "=r"(r[0]), "=r"(r[1]), "=r"(r[2]), "=r"(r[3]) : "r"(addr));
}
__device__ __forceinline__ void sts128(uint32_t addr, uint4 v) {
    asm volatile("st.shared.v4.b32 [%0], {%1,%2,%3,%4};"
                 :: "r"(addr), "r"(v.x), "r"(v.y), "r"(v.z), "r"(v.w) : "memory");
}
__device__ __forceinline__ void mma16816(float* d, const uint32_t* a, uint32_t b0, uint32_t b1) {
    asm volatile("mma.sync.aligned.m16n8k16.row.col.f32.bf16.bf16.f32 "
                 "{%0,%1,%2,%3}, {%4,%5,%6,%7}, {%8,%9}, {%0,%1,%2,%3};"
                 : "+f"(d[0]), "+f"(d[1]), "+f"(d[2]), "+f"(d[3])
                 : "r"(a[0]), "r"(a[1]), "r"(a[2]), "r"(a[3]), "r"(b0), "r"(b1));
}
__device__ __forceinline__ void splitf(float v, bf16& h, bf16& l) {
    h = __float2bfloat16(v);
    l = __float2bfloat16(v - __bfloat162float(h));
}

// ---------------- bf16-split tensor-core GEMM (R8 structure — measured best) ----------------
// C[M,N] = (Ah+Al)[M,K] @ (Bh+Bl)[N,K]^T, fp32 accum; 3 passes per k16: hh, hl, lh.
// skip_lh=1: A exact in bf16 -> lh pass adds exact zeros -> skip (value-identical).
// qkmerge=1: blockIdx.z==1 switches to (Bh2,Bl2,bias2,Ch2,Cl2) — Q and K projections
// in one launch; per-element arithmetic identical to two separate launches.
#define ROWB 80
#define BUFB (128 * ROWB)
#define STGB (4 * BUFB)
#define BG_SMEM (2 * STGB)

__global__ __launch_bounds__(256, 2)
void bgemm(const bf16* __restrict__ Ahg, const bf16* __restrict__ Alg,
           const bf16* __restrict__ Bhg, const bf16* __restrict__ Blg,
           const float* __restrict__ biasg,
           float* __restrict__ Cf, bf16* __restrict__ Chg, bf16* __restrict__ Clg,
           int K, int lda, int ldb, int ldc,
           long long sA, long long sB, long long sC,
           int headmode, int D, int dk, int skip_lh,
           int qkmerge,
           const bf16* __restrict__ Bh2g, const bf16* __restrict__ Bl2g,
           const float* __restrict__ bias2g, bf16* __restrict__ Ch2g, bf16* __restrict__ Cl2g) {
    extern __shared__ char smraw[];
    const uint32_t sb = smem_u32(smraw);

    const int tid = threadIdx.x, lane = tid & 31, wid = tid >> 5;
    const int m_off = (wid >> 2) * 64, n_off = (wid & 3) * 32;
    const int rowBase = blockIdx.y << 7, colBase = blockIdx.x << 7;

    const float* bias = biasg;
    bf16 *Ch = Chg, *Cl = Clg;
    const bf16 *Ah, *Al, *Bh, *Bl;
    size_t coff;
    if (headmode) {
        int bz = blockIdx.z, b = bz >> 3, h = bz & 7;
        size_t off = (size_t)b * 256 * D + (size_t)h * dk;
        Ah = Ahg + off; Al = Alg + off; Bh = Bhg + off; Bl = Blg + off;
        coff = (size_t)bz * sC;
    } else {
        Ah = Ahg + (size_t)blockIdx.z * sA; Al = Alg + (size_t)blockIdx.z * sA;
        if (qkmerge && blockIdx.z == 1) {
            Bh = Bh2g; Bl = Bl2g; bias = bias2g; Ch = Ch2g; Cl = Cl2g;
            coff = 0;
        } else {
            Bh = Bhg + (size_t)blockIdx.z * sB; Bl = Blg + (size_t)blockIdx.z * sB;
            coff = (size_t)blockIdx.z * sC;
        }
    }

    const int nch = K >> 5;

    auto ldg_half = [&](int ch, int half, uint4* st) {
#pragma unroll
        for (int i = 0; i < 4; ++i) {
            int c = tid + ((half * 4 + i) << 8);
            int buf = c >> 9, idx = c & 511;
            int row = idx >> 2, seg = idx & 3;
            const bf16* g;
            int ld;
            if (buf == 0)      { g = Ah; ld = lda; }
            else if (buf == 1) { g = Al; ld = lda; }
            else if (buf == 2) { g = Bh; ld = ldb; }
            else               { g = Bl; ld = ldb; }
            int grow = ((buf < 2) ? rowBase : colBase) + row;
            st[i] = *(const uint4*)(g + (size_t)grow * ld + (ch << 5) + (seg << 3));
        }
    };
    auto sts_half = [&](int half, int stage, const uint4* st) {
        uint32_t sbase = sb + stage * STGB;
#pragma unroll
        for (int i = 0; i < 4; ++i) {
            int c = tid + ((half * 4 + i) << 8);
            int buf = c >> 9, idx = c & 511;
            int row = idx >> 2, seg = idx & 3;
            sts128(sbase + buf * BUFB + row * ROWB + (seg << 4), st[i]);
        }
    };

    float acc[4][4][4];
#pragma unroll
    for (int a = 0; a < 4; ++a)
#pragma unroll
        for (int b = 0; b < 4; ++b)
#pragma unroll
            for (int c = 0; c < 4; ++c) acc[a][b][c] = 0.f;

    {
        uint4 p[4];
        ldg_half(0, 0, p);
        sts_half(0, 0, p);
        ldg_half(0, 1, p);
        sts_half(1, 0, p);
    }
    __syncthreads();

    uint4 stg[4];
    for (int ch = 0; ch < nch; ++ch) {
        const int st = ch & 1;
        const uint32_t sbase = sb + st * STGB;
        const uint32_t lrow = (uint32_t)(lane & 15) * ROWB + ((lane >> 4) << 4);
        const bool more = (ch + 1 < nch);

        if (more) ldg_half(ch + 1, 0, stg);

#pragma unroll
        for (int ks = 0; ks < 2; ++ks) {
            uint32_t kb = ks << 5;
            uint32_t afr[4][4], bfr[2][4];
            // pass 0: Ah * Bh
#pragma unroll
            for (int mt = 0; mt < 4; ++mt)
                ldsm4(afr[mt], sbase + (uint32_t)(m_off + mt * 16) * ROWB + lrow + kb);
#pragma unroll
            for (int p = 0; p < 2; ++p)
                ldsm4(bfr[p], sbase + 2 * BUFB + (uint32_t)(n_off + p * 16) * ROWB + lrow + kb);
#pragma unroll
            for (int mt = 0; mt < 4; ++mt)
#pragma unroll
                for (int nt = 0; nt < 4; ++nt)
                    mma16816(acc[mt][nt], afr[mt], bfr[nt >> 1][nt & 1], bfr[nt >> 1][(nt & 1) + 2]);
            // pass 1: Ah * Bl
#pragma unroll
            for (int p = 0; p < 2; ++p)
                ldsm4(bfr[p], sbase + 3 * BUFB + (uint32_t)(n_off + p * 16) * ROWB + lrow + kb);
#pragma unroll
            for (int mt = 0; mt < 4; ++mt)
#pragma unroll
                for (int nt = 0; nt < 4; ++nt)
                    mma16816(acc[mt][nt], afr[mt], bfr[nt >> 1][nt & 1], bfr[nt >> 1][(nt & 1) + 2]);
            // pass 2: Al * Bh  (skipped when Al==0 exactly — value-identical)
            if (!skip_lh) {
#pragma unroll
                for (int mt = 0; mt < 4; ++mt)
                    ldsm4(afr[mt], sbase + BUFB + (uint32_t)(m_off + mt * 16) * ROWB + lrow + kb);
#pragma unroll
                for (int p = 0; p < 2; ++p)
                    ldsm4(bfr[p], sbase + 2 * BUFB + (uint32_t)(n_off + p * 16) * ROWB + lrow + kb);
#pragma unroll
                for (int mt = 0; mt < 4; ++mt)
#pragma unroll
                    for (int nt = 0; nt < 4; ++nt)
                        mma16816(acc[mt][nt], afr[mt], bfr[nt >> 1][nt & 1], bfr[nt >> 1][(nt & 1) + 2]);
            }

            if (more) {
                if (ks == 0) {
                    sts_half(0, st ^ 1, stg);
                    ldg_half(ch + 1, 1, stg);
                } else {
                    sts_half(1, st ^ 1, stg);
                }
            }
        }
        __syncthreads();
    }

#pragma unroll
    for (int mt = 0; mt < 4; ++mt) {
#pragma unroll
        for (int nt = 0; nt < 4; ++nt) {
            int col = colBase + n_off + nt * 8 + (lane & 3) * 2;
            float b0 = 0.f, b1 = 0.f;
            if (bias) { b0 = bias[col]; b1 = bias[col + 1]; }
#pragma unroll
            for (int half = 0; half < 2; ++half) {
                int row = rowBase + m_off + mt * 16 + (lane >> 2) + half * 8;
                float v0 = acc[mt][nt][half * 2] + b0;
                float v1 = acc[mt][nt][half * 2 + 1] + b1;
                size_t ci = coff + (size_t)row * ldc + col;
                if (Cf) *(float2*)(Cf + ci) = make_float2(v0, v1);
                if (Ch) {
                    bf16 h0, l0, h1, l1;
                    splitf(v0, h0, l0); splitf(v1, h1, l1);
                    *(__nv_bfloat162*)(Ch + ci) = __nv_bfloat162(h0, h1);
                    *(__nv_bfloat162*)(Cl + ci) = __nv_bfloat162(l0, l1);
                }
            }
        }
    }
}

// ---------------- producers: split fp32 -> bf16 hi/lo ----------------
__global__ void copy_inputs_hl(const float* __restrict__ in, bf16* __restrict__ xh, bf16* __restrict__ xl) {
    int r = blockIdx.x, c = threadIdx.x * 4;
    float4 v = *(const float4*)(in + (size_t)r * INDIM_ + c);
    bf16 h[4], l[4];
    splitf(v.x, h[0], l[0]); splitf(v.y, h[1], l[1]);
    splitf(v.z, h[2], l[2]); splitf(v.w, h[3], l[3]);
    size_t o = (size_t)r * XLD + c;
    *(__nv_bfloat162*)(xh + o) = __nv_bfloat162(h[0], h[1]);
    *(__nv_bfloat162*)(xh + o + 2) = __nv_bfloat162(h[2], h[3]);
    *(__nv_bfloat162*)(xl + o) = __nv_bfloat162(l[0], l[1]);
    *(__nv_bfloat162*)(xl + o + 2) = __nv_bfloat162(l[2], l[3]);
}

__global__ void adjsplit_kernel(const float* __restrict__ adj, bf16* __restrict__ ah, bf16* __restrict__ al) {
    int idx = blockIdx.x * blockDim.x + threadIdx.x;
    float v = adj[idx];
    bf16 h, l;
    splitf(v, h, l);
    ah[idx] = h; al[idx] = l;
}

__global__ void transpose_w_hl(const float* __restrict__ src, bf16* __restrict__ dh,
                               bf16* __restrict__ dl, int K, int N) {
    __shared__ float t[32][33];
    int n0 = blockIdx.x * 32, k0 = blockIdx.y * 32;
    int x = threadIdx.x, y = threadIdx.y;
#pragma unroll
    for (int i = 0; i < 32; i += 8) t[y + i][x] = src[(size_t)(k0 + y + i) * N + n0 + x];
    __syncthreads();
#pragma unroll
    for (int i = 0; i < 32; i += 8) {
        float v = t[x][y + i];
        bf16 h, l;
        splitf(v, h, l);
        size_t o = (size_t)(n0 + y + i) * K + k0 + x;
        dh[o] = h; dl[o] = l;
    }
}

__global__ void transpose_b64_hl(const bf16* __restrict__ sh, const bf16* __restrict__ sl,
                                 bf16* __restrict__ dh, bf16* __restrict__ dl) {
    __shared__ bf16 th[32][33], tl[32][33];
    size_t zo = (size_t)blockIdx.z * 65536;
    int n0 = blockIdx.x * 32, k0 = blockIdx.y * 32;
    int x = threadIdx.x, y = threadIdx.y;
#pragma unroll
    for (int i = 0; i < 32; i += 8) {
        size_t o = zo + (size_t)(k0 + y + i) * 256 + n0 + x;
        th[y + i][x] = sh[o];
        tl[y + i][x] = sl[o];
    }
    __syncthreads();
#pragma unroll
    for (int i = 0; i < 32; i += 8) {
        size_t o = zo + (size_t)(n0 + y + i) * 256 + k0 + x;
        dh[o] = th[x][y + i];
        dl[o] = tl[x][y + i];
    }
}

// ---------------- mask dtype detection (parallel) + pad extraction ----------------
__global__ void reset_flags_kernel() {
    if (threadIdx.x < 3) g_maskflags[threadIdx.x] = 0;
}
__global__ void detect_mask_kernel(const unsigned int* __restrict__ w) {
    int fu8 = 0, ff32 = 0, fbf = 0;
    for (int i = blockIdx.x * blockDim.x + threadIdx.x; i < 1048576; i += gridDim.x * blockDim.x) {
        unsigned v = w[i];
        if (v == 0u || v == 1u) continue;
        if (v == 0x3F800000u) { ff32 = 1; continue; }
        unsigned b0 = v & 255u, b1 = (v >> 8) & 255u, b2 = (v >> 16) & 255u, b3 = v >> 24;
        if (b0 < 2u && b1 < 2u && b2 < 2u && b3 < 2u) { fu8 = 1; continue; }
        unsigned h0 = v & 0xFFFFu, h1 = v >> 16;
        if ((h0 == 0u || h0 == 0x3F80u) && (h1 == 0u || h1 == 0x3F80u)) fbf = 1;
    }
    if (fu8)  atomicOr(&g_maskflags[0], 1);
    if (ff32) atomicOr(&g_maskflags[1], 1);
    if (fbf)  atomicOr(&g_maskflags[2], 1);
}
__global__ void extract_pad_kernel(const void* __restrict__ mask, float* __restrict__ pad) {
    int idx = blockIdx.x * blockDim.x + threadIdx.x;
    int b = idx >> 8, i = idx & 255;
    size_t e = (size_t)b * 65536 + (size_t)i * 257;
    int kind;   // priority: bf16 > f32 > u8 > i32
    if (g_maskflags[2]) kind = 3;
    else if (g_maskflags[1]) kind = 2;
    else if (g_maskflags[0]) kind = 0;
    else kind = 1;
    float v;
    if (kind == 0)      v = ((const unsigned char*)mask)[e] ? 1.f : 0.f;
    else if (kind == 1) v = ((const int*)mask)[e] ? 1.f : 0.f;
    else if (kind == 2) v = (((const float*)mask)[e] != 0.f) ? 1.f : 0.f;
    else                v = (((const unsigned short*)mask)[e] != 0) ? 1.f : 0.f;
    pad[idx] = v;
}

// ---------------- elementwise ----------------
__global__ void rowsum_kernel(const float* __restrict__ A, float* __restrict__ denom) {
    int warp = threadIdx.x >> 5, lane = threadIdx.x & 31;
    int row = blockIdx.x * 8 + warp;
    const float4* p = (const float4*)(A + (size_t)row * 256);
    float4 v0 = p[lane], v1 = p[lane + 32];
    float s = v0.x + v0.y + v0.z + v0.w + v1.x + v1.y + v1.z + v1.w;
#pragma unroll
    for (int w = 16; w; w >>= 1) s += __shfl_xor_sync(0xffffffffu, s, w);
    if (lane == 0) denom[row] = s + 1.f;
}

__global__ void combine_hl_kernel(const float* __restrict__ t2,
                                  const bf16* __restrict__ xwh, const bf16* __restrict__ xwl,
                                  const float* __restrict__ bias, const float* __restrict__ denom,
                                  bf16* __restrict__ xh, bf16* __restrict__ xl, int coloff,
                                  float* __restrict__ outf) {
    int r = blockIdx.x, c = threadIdx.x;
    float bc = bias[c];
    float d = denom[r];
    size_t si = (size_t)r * 256 + c;
    float xw = __bfloat162float(xwh[si]) + __bfloat162float(xwl[si]);
    float v = (t2[si] + bc) / d;
    float o = fmaxf(v, 0.f) + xw + bc;
    if (outf) {
        outf[si] = o;
    } else {
        bf16 h, l;
        splitf(o, h, l);
        size_t di = (size_t)r * XLD + coloff + c;
        xh[di] = h; xl[di] = l;
    }
}

// ---------------- fused masked softmax + head sum (batched heads, 2 syncs) ----------------
__global__ __launch_bounds__(256)
void softmax_headsum_kernel(const float* __restrict__ Sc, const float* __restrict__ pad,
                            float* __restrict__ Aout, float scale) {
    int row = blockIdx.x;
    int b = row >> 8, qi = row & 255;
    int j = threadIdx.x;
    __shared__ float redm[64], reds[64];
    int warp = j >> 5, lane = j & 31;
    float padj = pad[b * 256 + j];
    float padq = pad[b * 256 + qi];
    bool valid = (padj == 0.f);
    const float* base = Sc + (((size_t)(b * 8)) << 16) + (size_t)qi * 256 + j;

    float s[8], m[8], e[8];
#pragma unroll
    for (int h = 0; h < 8; ++h) s[h] = base[(size_t)h << 16] * scale;
#pragma unroll
    for (int h = 0; h < 8; ++h) m[h] = valid ? s[h] : -3e38f;
#pragma unroll
    for (int w = 16; w; w >>= 1)
#pragma unroll
        for (int h = 0; h < 8; ++h) m[h] = fmaxf(m[h], __shfl_xor_sync(0xffffffffu, m[h], w));
    if (lane == 0) {
#pragma unroll
        for (int h = 0; h < 8; ++h) redm[h * 8 + warp] = m[h];
    }
    __syncthreads();
    float mx[8];
#pragma unroll
    for (int h = 0; h < 8; ++h) {
        float v = redm[h * 8];
#pragma unroll
        for (int w = 1; w < 8; ++w) v = fmaxf(v, redm[h * 8 + w]);
        mx[h] = v;
    }
#pragma unroll
    for (int h = 0; h < 8; ++h) e[h] = valid ? expf(s[h] - mx[h]) : 0.f;
    float t[8];
#pragma unroll
    for (int h = 0; h < 8; ++h) t[h] = e[h];
#pragma unroll
    for (int w = 16; w; w >>= 1)
#pragma unroll
        for (int h = 0; h < 8; ++h) t[h] += __shfl_xor_sync(0xffffffffu, t[h], w);
    if (lane == 0) {
#pragma unroll
        for (int h = 0; h < 8; ++h) reds[h * 8 + warp] = t[h];
    }
    __syncthreads();
    float acc = 0.f;
#pragma unroll
    for (int h = 0; h < 8; ++h) {
        float se = reds[h * 8];
#pragma unroll
        for (int w = 1; w < 8; ++w) se += reds[h * 8 + w];
        acc += e[h] / se;
    }
    Aout[(size_t)b * 65536 + (size_t)qi * 256 + j] = (padq != 0.f) ? 0.f : acc;
}

// ---------------- exact top-200 threshold (4-pass MSD radix select, R9 form) ----------------
__global__ __launch_bounds__(1024)
void topk_thresh_kernel(const float* __restrict__ a, float* __restrict__ thr) {
    int b = blockIdx.x;
    const float4* base = (const float4*)(a + (size_t)b * 65536);
    __shared__ unsigned hist[256];
    __shared__ unsigned s_prefix, s_rem, s_zcnt;
    if (threadIdx.x == 0) { s_prefix = 0; s_rem = TOPK_; s_zcnt = 0; }
    __syncthreads();
    for (int pass = 0; pass < 4; ++pass) {
        if (threadIdx.x < 256) hist[threadIdx.x] = 0;
        __syncthreads();
        int shift = 24 - pass * 8;
        unsigned pmask = pass ? (0xFFFFFFFFu << (shift + 8)) : 0u;
        unsigned pref = s_prefix & pmask;
        unsigned lz = 0;
        for (int i = threadIdx.x; i < 16384; i += 1024) {
            float4 v = base[i];
            unsigned kx[4] = {__float_as_uint(v.x), __float_as_uint(v.y),
                              __float_as_uint(v.z), __float_as_uint(v.w)};
#pragma unroll
            for (int t = 0; t < 4; ++t) {
                unsigned key = kx[t];
                if (key == 0u) { if (pass == 0) lz++; }
                else if ((key & pmask) == pref)
                    atomicAdd(&hist[(key >> shift) & 255u], 1u);
            }
        }
        if (pass == 0 && lz) atomicAdd(&s_zcnt, lz);
        __syncthreads();
        if (threadIdx.x == 0) {
            unsigned rem = s_rem, cum = 0;
            int chosen = 0;
            for (int d = 255; d >= 0; --d) {
                unsigned c = hist[d];
                if (d == 0 && ((s_prefix & pmask) == 0u)) c += s_zcnt;
                if (cum + c >= rem) { chosen = d; s_rem = rem - cum; break; }
                cum += c;
            }
            s_prefix |= (unsigned)chosen << shift;
        }
        __syncthreads();
    }
    if (threadIdx.x == 0) thr[b] = __uint_as_float(s_prefix);
}

// ---------------- top-k selection mask + new denom (R9 form, writes a2 hi/lo) ----------------
__global__ void maskdenom_kernel(const float* __restrict__ a, const float* __restrict__ thr,
                                 bf16* __restrict__ a2h, bf16* __restrict__ a2l,
                                 float* __restrict__ denom) {
    int b = blockIdx.y, i = blockIdx.x, j = threadIdx.x;
    const float* ab = a + (size_t)b * 65536;
    float th = thr[b];
    float va = ab[i * 256 + j];
    float vb = ab[j * 256 + i];
    float m = (i == j) ? 1.f : ((va >= th ? 1.f : 0.f) + (vb >= th ? 1.f : 0.f));
    float o = m * va;
    bf16 h, l;
    splitf(o, h, l);
    size_t oi = (size_t)b * 65536 + i * 256 + j;
    a2h[oi] = h; a2l[oi] = l;
    float s = o;
#pragma unroll
    for (int w = 16; w; w >>= 1) s += __shfl_xor_sync(0xffffffffu, s, w);
    __shared__ float ws[8];
    int warp = threadIdx.x >> 5, lane = threadIdx.x & 31;
    if (lane == 0) ws[warp] = s;
    __syncthreads();
    if (threadIdx.x == 0) {
        float t = 0.f;
#pragma unroll
        for (int w = 0; w < 8; ++w) t += ws[w];
        denom[b * 256 + i] = t + 1.f;
    }
}

// ---------------- host orchestration ----------------
extern "C" void kernel_launch(void* const* d_in, const int* in_sizes, int n_in,
                              void* d_out, int out_size) {
    const float* adj    = (const float*)d_in[0];
    const float* inputs = (const float*)d_in[1];
    const void*  smask  = d_in[2];
    const float* Ww[3]  = {(const float*)d_in[3], (const float*)d_in[5], (const float*)d_in[7]};
    const float* Wb[3]  = {(const float*)d_in[4], (const float*)d_in[6], (const float*)d_in[8]};
    const float* qw[2]  = {(const float*)d_in[9],  (const float*)d_in[13]};
    const float* qb[2]  = {(const float*)d_in[10], (const float*)d_in[14]};
    const float* kw[2]  = {(const float*)d_in[11], (const float*)d_in[15]};
    const float* kb[2]  = {(const float*)d_in[12], (const float*)d_in[16]};
    float* out = (float*)d_out;

    bf16 *xh, *xl, *qh, *ql, *kh, *kl, *a2h, *a2l, *adjh, *adjl;
    bf16 *xwh, *xwl, *xwth, *xwtl, *wth, *wtl;
    float *sc, *a, *t2, *denom, *thr, *pad;
    cudaGetSymbolAddress((void**)&xh, g_xh);    cudaGetSymbolAddress((void**)&xl, g_xl);
    cudaGetSymbolAddress((void**)&qh, g_qh);    cudaGetSymbolAddress((void**)&ql, g_ql);
    cudaGetSymbolAddress((void**)&kh, g_kh);    cudaGetSymbolAddress((void**)&kl, g_kl);
    cudaGetSymbolAddress((void**)&a2h, g_a2h);  cudaGetSymbolAddress((void**)&a2l, g_a2l);
    cudaGetSymbolAddress((void**)&adjh, g_adjh); cudaGetSymbolAddress((void**)&adjl, g_adjl);
    cudaGetSymbolAddress((void**)&xwh, g_xwh);  cudaGetSymbolAddress((void**)&xwl, g_xwl);
    cudaGetSymbolAddress((void**)&xwth, g_xwth); cudaGetSymbolAddress((void**)&xwtl, g_xwtl);
    cudaGetSymbolAddress((void**)&wth, g_wth);  cudaGetSymbolAddress((void**)&wtl, g_wtl);
    cudaGetSymbolAddress((void**)&sc, g_scores);
    cudaGetSymbolAddress((void**)&a, g_a);
    cudaGetSymbolAddress((void**)&t2, g_t2);
    cudaGetSymbolAddress((void**)&denom, g_denom);
    cudaGetSymbolAddress((void**)&thr, g_thr);
    cudaGetSymbolAddress((void**)&pad, g_pad);

    const long long oW0 = 0, oW1 = 131072, oW2 = 327680;
    const long long oQ0 = 589824, oK0 = 1179648, oQ1 = 1769472, oK1 = 2818048;

    cudaFuncSetAttribute(bgemm, cudaFuncAttributeMaxDynamicSharedMemorySize, BG_SMEM);

    dim3 tb(32, 8);
    // ---- preprocessing (4th launch = representative bgemm, for ncu) ----
    copy_inputs_hl<<<BS_, 128>>>(inputs, xh, xl);                          // 1
    reset_flags_kernel<<<1, 32>>>();                                       // 2
    transpose_w_hl<<<dim3(8, 16), tb>>>(Ww[0], wth + oW0, wtl + oW0, 512, 256);  // 3
    // 4: xw = x @ W0 (hi/lo out, no bias)  [PROFILED]
    bgemm<<<dim3(2, 128, 1), 256, BG_SMEM>>>(xh, xl, wth + oW0, wtl + oW0, nullptr,
                                             nullptr, xwh, xwl, 512, XLD, 512, 256,
                                             0, 0, 0, 0, 0, 0, 0,
                                             0, nullptr, nullptr, nullptr, nullptr, nullptr);
    detect_mask_kernel<<<256, 256>>>((const unsigned int*)smask);
    extract_pad_kernel<<<64, 256>>>(smask, pad);
    adjsplit_kernel<<<B_ * S_ * S_ / 1024, 1024>>>(adj, adjh, adjl);
    rowsum_kernel<<<BS_ / 8, 256>>>(adj, denom);
    transpose_w_hl<<<dim3(8, 24), tb>>>(Ww[1], wth + oW1, wtl + oW1, 768, 256);
    transpose_w_hl<<<dim3(8, 32), tb>>>(Ww[2], wth + oW2, wtl + oW2, 1024, 256);
    transpose_w_hl<<<dim3(24, 24), tb>>>(qw[0], wth + oQ0, wtl + oQ0, 768, 768);
    transpose_w_hl<<<dim3(24, 24), tb>>>(kw[0], wth + oK0, wtl + oK0, 768, 768);
    transpose_w_hl<<<dim3(32, 32), tb>>>(qw[1], wth + oQ1, wtl + oQ1, 1024, 1024);
    transpose_w_hl<<<dim3(32, 32), tb>>>(kw[1], wth + oK1, wtl + oK1, 1024, 1024);

    const long long oWT[3] = {oW0, oW1, oW2};
    const long long oQT[2] = {oQ0, oQ1};
    const long long oKT[2] = {oK0, oK1};

    // ---- layer 0 ----
    transpose_b64_hl<<<dim3(8, 8, 64), tb>>>(xwh, xwl, xwth, xwtl);
    bgemm<<<dim3(2, 2, 64), 256, BG_SMEM>>>(adjh, adjl, xwth, xwtl, nullptr,
                                            t2, nullptr, nullptr, 256, 256, 256, 256,
                                            65536LL, 65536LL, 65536LL, 0, 0, 0, 1,
                                            0, nullptr, nullptr, nullptr, nullptr, nullptr);
    combine_hl_kernel<<<BS_, 256>>>(t2, xwh, xwl, Wb[0], denom, xh, xl, 512, nullptr);

    // ---- layers 1 and 2 ----
    for (int L = 1; L <= 2; ++L) {
        int D = INDIM_ + 256 * L;   // 768, 1024
        int dk = D / HEADS_;        // 96, 128
        int ai = L - 1;
        // merged Q (z=0) + K (z=1) projection in ONE launch (wave packing; per-element identical)
        bgemm<<<dim3(D / 128, 128, 2), 256, BG_SMEM>>>(xh, xl, wth + oQT[ai], wtl + oQT[ai], qb[ai],
                                                       nullptr, qh, ql, D, XLD, D, D,
                                                       0, 0, 0, 0, 0, 0, 0,
                                                       1, wth + oKT[ai], wtl + oKT[ai], kb[ai], kh, kl);
        bgemm<<<dim3(2, 2, B_ * HEADS_), 256, BG_SMEM>>>(qh, ql, kh, kl, nullptr,
                                                         sc, nullptr, nullptr, dk, D, D, 256,
                                                         0, 0, 65536LL, 1, D, dk, 0,
                                                         0, nullptr, nullptr, nullptr, nullptr, nullptr);
        softmax_headsum_kernel<<<BS_, 256>>>(sc, pad, a, 1.0f / sqrtf((float)dk));
        topk_thresh_kernel<<<B_, 1024>>>(a, thr);
        maskdenom_kernel<<<dim3(S_, B_), 256>>>(a, thr, a2h, a2l, denom);
        bgemm<<<dim3(2, 128, 1), 256, BG_SMEM>>>(xh, xl, wth + oWT[L], wtl + oWT[L], nullptr,
                                                 nullptr, xwh, xwl, D, XLD, D, 256,
                                                 0, 0, 0, 0, 0, 0, 0,
                                                 0, nullptr, nullptr, nullptr, nullptr, nullptr);
        transpose_b64_hl<<<dim3(8, 8, 64), tb>>>(xwh, xwl, xwth, xwtl);
        bgemm<<<dim3(2, 2, 64), 256, BG_SMEM>>>(a2h, a2l, xwth, xwtl, nullptr,
                                                t2, nullptr, nullptr, 256, 256, 256, 256,
                                                65536LL, 65536LL, 65536LL, 0, 0, 0, 0,
                                                0, nullptr, nullptr, nullptr, nullptr, nullptr);
        if (L < 2)
            combine_hl_kernel<<<BS_, 256>>>(t2, xwh, xwl, Wb[L], denom, xh, xl, 512 + 256 * L, nullptr);
        else
            combine_hl_kernel<<<BS_, 256>>>(t2, xwh, xwl, Wb[L], denom, nullptr, nullptr, 0, out);
    }
}